// round 8
// baseline (speedup 1.0000x reference)
#include <cuda_runtime.h>
#include <cuda_bf16.h>
#include <cuda_fp16.h>
#include <cstdint>
#include <cstring>

// ---------------------------------------------------------------------------
// Fused MoE: T=1024 tokens, D=1024, I=512, E=16 experts top-4 + shared expert.
//   gate -> sched -> place -> fused per 32-row tile (2 blocks/SM):
//     Phase 1: GEMM1 (tf32 mma) + silu*mul -> h tile (fp16) in SMEM
//     Phase 2: GEMM2 (fp16 mma m16n8k16) -> weighted atomicAdd into out
//   TK=32 k-steps, depth-3 cp.async pipeline; occupancy-2 hides latency.
// ---------------------------------------------------------------------------

#define T_TOKENS 1024
#define DIM      1024
#define INTER    512
#define NEXP     16
#define TOPK     4
#define NROWS    5120
#define TMF      32
#define MAXT     176             // <= 16 + 4096/32 + 1024/32
#define TK       32
#define TSTR     36              // stage row stride (uint32): 32 + 4 pad
#define HSTR2W   260             // Hs row stride in half2 words (520 halves)
#define NSTAGE   3
#define P1A      4608            // A array bytes within a stage (32x36x4)
#define P1B      9216            // Bg / Bu array bytes (64x36x4)
#define P1STAGE  23040           // per phase-1 stage
#define P2STAGE  18432           // per phase-2 stage (128x36x4)

struct TileDesc { int e; int row0; int rows; };

__device__ int      g_counts[NEXP];
__device__ int      g_off[NEXP + 1];
__device__ int      g_idx[T_TOKENS * TOPK];
__device__ float    g_w[T_TOKENS * TOPK];
__device__ int      g_row_token[NROWS];
__device__ float    g_row_weight[NROWS];
__device__ TileDesc g_tiles[MAXT];
__device__ int      g_ntiles;

// ---- shared-memory layout (102656 B -> 2 blocks/SM) ------------------------
#define SM_HS     0              // Hs[32][520] fp16 = 33280 B
#define SM_ST     33280          // 3 stages (ph1 23040 / ph2 18432 each)
#define SM_RTOK   102400
#define SM_RWT    102528
#define SM_TOTAL  102656

// ---------------------------------------------------------------------------
__global__ void init_kernel() {
    if (threadIdx.x < NEXP) g_counts[threadIdx.x] = 0;
}

// ---------------------------------------------------------------------------
__global__ __launch_bounds__(256)
void gate_kernel(const float* __restrict__ x,
                 const float* __restrict__ gw,
                 const float* __restrict__ gb) {
    const int token = (blockIdx.x * blockDim.x + threadIdx.x) >> 5;
    const int lane  = threadIdx.x & 31;
    if (token >= T_TOKENS) return;
    const float* xt = x + (size_t)token * DIM;

    float myscore = 0.f;
    for (int e = 0; e < NEXP; e++) {
        const float* we = gw + e * DIM;
        float p = 0.f;
        #pragma unroll 4
        for (int d = lane; d < DIM; d += 32) p += xt[d] * we[d];
        #pragma unroll
        for (int o = 16; o; o >>= 1) p += __shfl_xor_sync(0xffffffffu, p, o);
        if (lane == e) myscore = 1.0f / (1.0f + expf(-p));
    }
    float mybiased = (lane < NEXP) ? (myscore + gb[lane]) : -1e30f;

    float sum = 0.f;
    int   kidx[TOPK]; float kw[TOPK];
    #pragma unroll
    for (int k = 0; k < TOPK; k++) {
        float v = mybiased; int bl = lane;
        #pragma unroll
        for (int o = 16; o; o >>= 1) {
            float ov = __shfl_xor_sync(0xffffffffu, v, o);
            int   ol = __shfl_xor_sync(0xffffffffu, bl, o);
            if (ov > v || (ov == v && ol < bl)) { v = ov; bl = ol; }
        }
        float sc = __shfl_sync(0xffffffffu, myscore, bl);
        kidx[k] = bl; kw[k] = sc; sum += sc;
        if (lane == bl) mybiased = -1e30f;
    }
    const float s = 2.5f / sum;
    if (lane == 0) {
        #pragma unroll
        for (int k = 0; k < TOPK; k++) {
            g_idx[token * TOPK + k] = kidx[k];
            g_w[token * TOPK + k]   = kw[k] * s;
            atomicAdd(&g_counts[kidx[k]], 1);
        }
        g_row_token[4096 + token]  = token;
        g_row_weight[4096 + token] = 1.0f;
    }
}

// ---------------------------------------------------------------------------
__global__ void sched_kernel() {
    int off = 0, nt = 0;
    for (int e = 0; e < NEXP; e++) {
        g_off[e] = off;
        int c = g_counts[e];
        for (int i = 0; i < c; i += TMF) {
            g_tiles[nt].e    = e;
            g_tiles[nt].row0 = off + i;
            g_tiles[nt].rows = min(TMF, c - i);
            nt++;
        }
        off += c;
    }
    g_off[NEXP] = off;
    for (int i = 0; i < T_TOKENS; i += TMF) {
        g_tiles[nt].e = NEXP; g_tiles[nt].row0 = 4096 + i; g_tiles[nt].rows = TMF;
        nt++;
    }
    g_ntiles = nt;
}

// ---------------------------------------------------------------------------
__global__ void place_kernel() {
    __shared__ int s[T_TOKENS];
    int e = blockIdx.x, t = threadIdx.x;
    int myk = -1;
    #pragma unroll
    for (int k = 0; k < TOPK; k++)
        if (g_idx[t * TOPK + k] == e) myk = k;
    s[t] = (myk >= 0) ? 1 : 0;
    __syncthreads();
    for (int off = 1; off < T_TOKENS; off <<= 1) {
        int v = (t >= off) ? s[t - off] : 0;
        __syncthreads();
        s[t] += v;
        __syncthreads();
    }
    if (myk >= 0) {
        int row = g_off[e] + s[t] - 1;
        g_row_token[row]  = t;
        g_row_weight[row] = g_w[t * TOPK + myk];
    }
}

// ---------------------------------------------------------------------------
__device__ __forceinline__ uint32_t f2tf32(float f) {
    uint32_t r;
    asm("cvt.rna.tf32.f32 %0, %1;" : "=r"(r) : "f"(f));
    return r;
}
__device__ __forceinline__ uint32_t lds_tf32(const uint32_t* p) {
    return f2tf32(__uint_as_float(*p));
}
__device__ __forceinline__ uint32_t pack_f16x2(float a, float b) {
    uint32_t r;
    asm("cvt.rn.f16x2.f32 %0, %1, %2;" : "=r"(r) : "f"(b), "f"(a));
    return r;
}

__device__ __forceinline__ void mma_tf32(float* d, const uint32_t* a, const uint32_t* b) {
    asm volatile(
        "mma.sync.aligned.m16n8k8.row.col.f32.tf32.tf32.f32 "
        "{%0,%1,%2,%3},{%4,%5,%6,%7},{%8,%9},{%0,%1,%2,%3};"
        : "+f"(d[0]), "+f"(d[1]), "+f"(d[2]), "+f"(d[3])
        : "r"(a[0]), "r"(a[1]), "r"(a[2]), "r"(a[3]), "r"(b[0]), "r"(b[1]));
}
__device__ __forceinline__ void mma_f16(float* d, const uint32_t* a, const uint32_t* b) {
    asm volatile(
        "mma.sync.aligned.m16n8k16.row.col.f32.f16.f16.f32 "
        "{%0,%1,%2,%3},{%4,%5,%6,%7},{%8,%9},{%0,%1,%2,%3};"
        : "+f"(d[0]), "+f"(d[1]), "+f"(d[2]), "+f"(d[3])
        : "r"(a[0]), "r"(a[1]), "r"(a[2]), "r"(a[3]), "r"(b[0]), "r"(b[1]));
}

__device__ __forceinline__ void cp16(uint32_t smem_dst, const void* gsrc) {
    asm volatile("cp.async.ca.shared.global [%0], [%1], 16;\n"
                 :: "r"(smem_dst), "l"(gsrc));
}
__device__ __forceinline__ void cp_commit() {
    asm volatile("cp.async.commit_group;\n");
}
__device__ __forceinline__ void cp_wait1() {
    asm volatile("cp.async.wait_group 1;\n");
}

// ---------------------------------------------------------------------------
// Fused expert kernel: one 32-row tile per block, 256 threads, 2 blocks/SM.
__global__ __launch_bounds__(256, 2)
void fused_kernel(const float* __restrict__ x,
                  const float* __restrict__ w13,
                  const float* __restrict__ w2,
                  const float* __restrict__ w13_s,
                  const float* __restrict__ w2_s,
                  float* __restrict__ out) {
    const int tile = blockIdx.x;
    if (tile >= g_ntiles) return;
    const TileDesc td = g_tiles[tile];
    const int row0 = td.row0, rows = td.rows;
    const float* B1 = (td.e < NEXP) ? (w13 + (size_t)td.e * (2 * INTER) * DIM) : w13_s;
    const float* B2 = (td.e < NEXP) ? (w2  + (size_t)td.e * DIM * INTER)       : w2_s;

    extern __shared__ char smem[];
    uint32_t* Hs   = (uint32_t*)(smem + SM_HS);     // [32][HSTR2W] half2 words
    char*     ST   = smem + SM_ST;
    int*      rtok = (int*)(smem + SM_RTOK);
    float*    rwt  = (float*)(smem + SM_RWT);

    const int tid  = threadIdx.x;
    const int lane = tid & 31, warp = tid >> 5;
    const int wm = warp >> 2, wn = warp & 3;        // 2 (m, 16 rows each) x 4 (n)
    const int g  = lane >> 2, tg = lane & 3;

    if (tid < TMF) {
        bool v = tid < rows;
        rtok[tid] = v ? g_row_token[row0 + tid] : 0;
        rwt[tid]  = v ? g_row_weight[row0 + tid] : 0.f;
    }
    __syncthreads();

    const uint32_t stBase = (uint32_t)__cvta_generic_to_shared(ST);

    // ---- phase-1 loader geometry: A 256 slots (1/thr), Bg/Bu 512 (2/thr) ---
    const int ra  = tid >> 3, ca = (tid & 7) * 4;     // A: row 0..31
    const int rb0 = tid >> 3, rb1 = rb0 + 32;         // B: rows r, r+32
    const int cb  = (tid & 7) * 4;
    const float* aSrc = x + (size_t)rtok[ra] * DIM + ca;
    const uint32_t dA  = stBase + (ra * TSTR + ca) * 4;
    const uint32_t dG0 = stBase + P1A + (rb0 * TSTR + cb) * 4;
    const uint32_t dG1 = stBase + P1A + (rb1 * TSTR + cb) * 4;
    const uint32_t dU0 = dG0 + P1B;
    const uint32_t dU1 = dG1 + P1B;

    // ======================= Phase 1: h = silu(x@Wg^T) * (x@Wu^T) ==========
    for (int nc = 0; nc < 8; nc++) {                 // 64 gate + 64 up cols
        float accG[2][4], accU[2][4];
        #pragma unroll
        for (int ni = 0; ni < 2; ni++)
            #pragma unroll
            for (int q = 0; q < 4; q++) { accG[ni][q] = 0.f; accU[ni][q] = 0.f; }

        const float* gSrc0 = B1 + (size_t)(nc * 64 + rb0) * DIM + cb;
        const float* gSrc1 = B1 + (size_t)(nc * 64 + rb1) * DIM + cb;
        const float* uSrc0 = gSrc0 + (size_t)512 * DIM;
        const float* uSrc1 = gSrc1 + (size_t)512 * DIM;

        __syncthreads();            // stage buffers free (prev chunk done)
        #pragma unroll
        for (int s = 0; s < NSTAGE - 1; s++) {       // prologue: stages 0,1
            const int off = s * TK;
            const uint32_t sb = s * P1STAGE;
            cp16(dA + sb, aSrc + off);
            cp16(dG0 + sb, gSrc0 + off); cp16(dG1 + sb, gSrc1 + off);
            cp16(dU0 + sb, uSrc0 + off); cp16(dU1 + sb, uSrc1 + off);
            cp_commit();
        }

        #pragma unroll 1
        for (int it = 0; it < DIM / TK; it++) {      // 32 iterations
            cp_wait1();
            __syncthreads();
            if (it + NSTAGE - 1 < DIM / TK) {
                const int off = (it + NSTAGE - 1) * TK;
                const uint32_t sb = ((it + NSTAGE - 1) % 3) * P1STAGE;
                cp16(dA + sb, aSrc + off);
                cp16(dG0 + sb, gSrc0 + off); cp16(dG1 + sb, gSrc1 + off);
                cp16(dU0 + sb, uSrc0 + off); cp16(dU1 + sb, uSrc1 + off);
            }
            cp_commit();
            const uint32_t* AsP = (const uint32_t*)(ST + (it % 3) * P1STAGE);
            const uint32_t* BgP = (const uint32_t*)(ST + (it % 3) * P1STAGE + P1A);
            const uint32_t* BuP = (const uint32_t*)(ST + (it % 3) * P1STAGE + P1A + P1B);
            #pragma unroll
            for (int ks = 0; ks < 4; ks++) {
                const int kk = ks * 8;
                uint32_t af[4], bg[2][2], bu[2][2];
                const int r = wm * 16;
                af[0] = lds_tf32(&AsP[(r + g    ) * TSTR + kk + tg]);
                af[1] = lds_tf32(&AsP[(r + g + 8) * TSTR + kk + tg]);
                af[2] = lds_tf32(&AsP[(r + g    ) * TSTR + kk + tg + 4]);
                af[3] = lds_tf32(&AsP[(r + g + 8) * TSTR + kk + tg + 4]);
                #pragma unroll
                for (int ni = 0; ni < 2; ni++) {
                    int c = wn * 16 + ni * 8 + g;
                    bg[ni][0] = lds_tf32(&BgP[c * TSTR + kk + tg]);
                    bg[ni][1] = lds_tf32(&BgP[c * TSTR + kk + tg + 4]);
                    bu[ni][0] = lds_tf32(&BuP[c * TSTR + kk + tg]);
                    bu[ni][1] = lds_tf32(&BuP[c * TSTR + kk + tg + 4]);
                }
                #pragma unroll
                for (int ni = 0; ni < 2; ni++) {
                    mma_tf32(accG[ni], af, bg[ni]);
                    mma_tf32(accU[ni], af, bu[ni]);
                }
            }
        }

        // epilogue: h = silu(g)*u -> Hs fp16
        {
            const int r0 = wm * 16 + g, r1 = r0 + 8;
            #pragma unroll
            for (int ni = 0; ni < 2; ni++) {
                int c = nc * 64 + wn * 16 + ni * 8 + 2 * tg;
                float g0 = accG[ni][0], g1 = accG[ni][1];
                float h0 = (g0 / (1.0f + expf(-g0))) * accU[ni][0];
                float h1 = (g1 / (1.0f + expf(-g1))) * accU[ni][1];
                Hs[r0 * HSTR2W + (c >> 1)] = pack_f16x2(h0, h1);
                float g2 = accG[ni][2], g3 = accG[ni][3];
                float h2 = (g2 / (1.0f + expf(-g2))) * accU[ni][2];
                float h3 = (g3 / (1.0f + expf(-g3))) * accU[ni][3];
                Hs[r1 * HSTR2W + (c >> 1)] = pack_f16x2(h2, h3);
            }
        }
    }

    // ======================= Phase 2: y = (h @ W2^T) * rowwt ===============
    // loader: 1024 slots (128 rows x 8 chunks), 4 per thread
    const int r2[4] = { tid >> 3, (tid + 256) >> 3, (tid + 512) >> 3, (tid + 768) >> 3 };
    const int c2v   = (tid & 7) * 4;

    for (int nb = 0; nb < 8; nb++) {                 // 128-col chunks of DIM
        const int n0 = nb * 128;
        float acc[4][4];
        #pragma unroll
        for (int ni = 0; ni < 4; ni++)
            #pragma unroll
            for (int q = 0; q < 4; q++) acc[ni][q] = 0.f;

        const float* bSrc[4];
        uint32_t dB[4];
        #pragma unroll
        for (int i = 0; i < 4; i++) {
            bSrc[i] = B2 + (size_t)(n0 + r2[i]) * INTER + c2v;
            dB[i]   = stBase + (r2[i] * TSTR + c2v) * 4;
        }

        __syncthreads();
        #pragma unroll
        for (int s = 0; s < NSTAGE - 1; s++) {
            const int off = s * TK;
            const uint32_t sb = s * P2STAGE;
            #pragma unroll
            for (int i = 0; i < 4; i++) cp16(dB[i] + sb, bSrc[i] + off);
            cp_commit();
        }

        #pragma unroll 1
        for (int it = 0; it < INTER / TK; it++) {    // 16 iterations
            cp_wait1();
            __syncthreads();
            if (it + NSTAGE - 1 < INTER / TK) {
                const int off = (it + NSTAGE - 1) * TK;
                const uint32_t sb = ((it + NSTAGE - 1) % 3) * P2STAGE;
                #pragma unroll
                for (int i = 0; i < 4; i++) cp16(dB[i] + sb, bSrc[i] + off);
            }
            cp_commit();
            const float* BsP = (const float*)(ST + (it % 3) * P2STAGE);
            const int kt = it * TK;
            #pragma unroll
            for (int ks = 0; ks < 2; ks++) {         // two k16 sub-steps
                const int kk = ks * 16;
                uint32_t af[4], bf[4][2];
                const int r = wm * 16;
                const int h0 = (kt + kk) >> 1;
                af[0] = Hs[(r + g    ) * HSTR2W + h0 + tg];
                af[1] = Hs[(r + g + 8) * HSTR2W + h0 + tg];
                af[2] = Hs[(r + g    ) * HSTR2W + h0 + 4 + tg];
                af[3] = Hs[(r + g + 8) * HSTR2W + h0 + 4 + tg];
                #pragma unroll
                for (int ni = 0; ni < 4; ni++) {
                    int c = wn * 32 + ni * 8 + g;
                    const float* row = BsP + c * TSTR + kk;
                    float2 p0 = *(const float2*)(row + 2 * tg);
                    float2 p1 = *(const float2*)(row + 8 + 2 * tg);
                    bf[ni][0] = pack_f16x2(p0.x, p0.y);
                    bf[ni][1] = pack_f16x2(p1.x, p1.y);
                }
                #pragma unroll
                for (int ni = 0; ni < 4; ni++)
                    mma_f16(acc[ni], af, bf[ni]);
            }
        }

        // epilogue: weighted atomic accumulate into out
        {
            const int r0 = wm * 16 + g, r1 = r0 + 8;
            float w0 = rwt[r0], w1 = rwt[r1];
            int   t0 = rtok[r0], t1 = rtok[r1];
            #pragma unroll
            for (int ni = 0; ni < 4; ni++) {
                int col = n0 + wn * 32 + ni * 8 + 2 * tg;
                float* q0 = out + (size_t)t0 * DIM + col;
                float* q1 = out + (size_t)t1 * DIM + col;
                atomicAdd(q0 + 0, acc[ni][0] * w0);
                atomicAdd(q0 + 1, acc[ni][1] * w0);
                atomicAdd(q1 + 0, acc[ni][2] * w1);
                atomicAdd(q1 + 1, acc[ni][3] * w1);
            }
        }
    }
}

// ---------------------------------------------------------------------------
namespace {
struct EagerInit {
    EagerInit() {
        cudaFuncAttributes a;
        (void)cudaFuncGetAttributes(&a, (const void*)init_kernel);
        (void)cudaFuncGetAttributes(&a, (const void*)gate_kernel);
        (void)cudaFuncGetAttributes(&a, (const void*)sched_kernel);
        (void)cudaFuncGetAttributes(&a, (const void*)place_kernel);
        (void)cudaFuncGetAttributes(&a, (const void*)fused_kernel);
        (void)cudaFuncSetAttribute((const void*)fused_kernel,
                                   cudaFuncAttributeMaxDynamicSharedMemorySize, SM_TOTAL);
        int zeros[NEXP];
        memset(zeros, 0, sizeof(zeros));
        (void)cudaMemcpyToSymbol(g_counts, zeros, sizeof(zeros));
        init_kernel<<<1, 32>>>();
        (void)cudaDeviceSynchronize();
        (void)cudaGetLastError();
    }
};
static EagerInit eager_init_instance;
}  // namespace

// ---------------------------------------------------------------------------
extern "C" void kernel_launch(void* const* d_in, const int* in_sizes, int n_in,
                              void* d_out, int out_size) {
    const float* x     = (const float*)d_in[0];
    const float* gw    = (const float*)d_in[2];
    const float* gb    = (const float*)d_in[3];
    const float* w13   = (const float*)d_in[4];
    const float* w2    = (const float*)d_in[5];
    const float* w13_s = (const float*)d_in[6];
    const float* w2_s  = (const float*)d_in[7];
    float* out = (float*)d_out;

    (void)cudaFuncSetAttribute((const void*)fused_kernel,
                               cudaFuncAttributeMaxDynamicSharedMemorySize, SM_TOTAL);

    cudaMemsetAsync(out, 0, (size_t)out_size * sizeof(float), 0);
    init_kernel<<<1, 32>>>();
    gate_kernel<<<T_TOKENS / 8, 256>>>(x, gw, gb);
    sched_kernel<<<1, 1>>>();
    place_kernel<<<NEXP, T_TOKENS>>>();
    fused_kernel<<<MAXT, 256, SM_TOTAL>>>(x, w13, w2, w13_s, w2_s, out);
}

// round 9
// speedup vs baseline: 1.1837x; 1.1837x over previous
#include <cuda_runtime.h>
#include <cuda_bf16.h>
#include <cuda_fp16.h>
#include <cstdint>
#include <cstring>

// ---------------------------------------------------------------------------
// Fused MoE: T=1024 tokens, D=1024, I=512, E=16 experts top-4 + shared expert.
//   fused per 64-row tile, 512 threads (16 warps):
//     Phase 1: GEMM1 (tf32 mma) + silu*mul -> h tile (fp16) in SMEM
//     Phase 2: GEMM2 (fp16 mma m16n8k16) -> weighted atomicAdd into out
//   TK=32, depth-4 cp.async pipeline, CONTINUOUS across n-chunks (flat step).
// ---------------------------------------------------------------------------

#define T_TOKENS 1024
#define DIM      1024
#define INTER    512
#define NEXP     16
#define TOPK     4
#define NROWS    5120
#define TMF      64
#define MAXT     96
#define TK       32
#define TSTR     36              // stage row stride (uint32): 32 + 4 pad
#define HSTR2W   260             // Hs row stride in half2 words (520 halves)
#define NSTAGE   4
#define P1ARR    9216            // one array (64x36x4 B) within a ph1 stage
#define P1STAGE  27648           // A+G+U per stage
#define P2STAGE  18432           // 128x36x4 per ph2 stage

struct TileDesc { int e; int row0; int rows; };

__device__ int      g_counts[NEXP];
__device__ int      g_off[NEXP + 1];
__device__ int      g_idx[T_TOKENS * TOPK];
__device__ float    g_w[T_TOKENS * TOPK];
__device__ int      g_row_token[NROWS];
__device__ float    g_row_weight[NROWS];
__device__ TileDesc g_tiles[MAXT];
__device__ int      g_ntiles;

// ---- shared-memory layout (177664 B, 1 block/SM) ---------------------------
#define SM_HS     0              // Hs[64][520] fp16 = 66560 B
#define SM_ST     66560          // 4 stages x 27648 = 110592 B
#define SM_RTOK   177152
#define SM_RWT    177408
#define SM_TOTAL  177664

// ---------------------------------------------------------------------------
__global__ void init_kernel() {
    if (threadIdx.x < NEXP) g_counts[threadIdx.x] = 0;
}

// ---------------------------------------------------------------------------
__global__ __launch_bounds__(256)
void gate_kernel(const float* __restrict__ x,
                 const float* __restrict__ gw,
                 const float* __restrict__ gb) {
    const int token = (blockIdx.x * blockDim.x + threadIdx.x) >> 5;
    const int lane  = threadIdx.x & 31;
    if (token >= T_TOKENS) return;
    const float* xt = x + (size_t)token * DIM;

    float myscore = 0.f;
    for (int e = 0; e < NEXP; e++) {
        const float* we = gw + e * DIM;
        float p = 0.f;
        #pragma unroll 4
        for (int d = lane; d < DIM; d += 32) p += xt[d] * we[d];
        #pragma unroll
        for (int o = 16; o; o >>= 1) p += __shfl_xor_sync(0xffffffffu, p, o);
        if (lane == e) myscore = 1.0f / (1.0f + expf(-p));
    }
    float mybiased = (lane < NEXP) ? (myscore + gb[lane]) : -1e30f;

    float sum = 0.f;
    int   kidx[TOPK]; float kw[TOPK];
    #pragma unroll
    for (int k = 0; k < TOPK; k++) {
        float v = mybiased; int bl = lane;
        #pragma unroll
        for (int o = 16; o; o >>= 1) {
            float ov = __shfl_xor_sync(0xffffffffu, v, o);
            int   ol = __shfl_xor_sync(0xffffffffu, bl, o);
            if (ov > v || (ov == v && ol < bl)) { v = ov; bl = ol; }
        }
        float sc = __shfl_sync(0xffffffffu, myscore, bl);
        kidx[k] = bl; kw[k] = sc; sum += sc;
        if (lane == bl) mybiased = -1e30f;
    }
    const float s = 2.5f / sum;
    if (lane == 0) {
        #pragma unroll
        for (int k = 0; k < TOPK; k++) {
            g_idx[token * TOPK + k] = kidx[k];
            g_w[token * TOPK + k]   = kw[k] * s;
            atomicAdd(&g_counts[kidx[k]], 1);
        }
        g_row_token[4096 + token]  = token;
        g_row_weight[4096 + token] = 1.0f;
    }
}

// ---------------------------------------------------------------------------
__global__ void sched_kernel() {
    int off = 0, nt = 0;
    for (int e = 0; e < NEXP; e++) {
        g_off[e] = off;
        int c = g_counts[e];
        for (int i = 0; i < c; i += TMF) {
            g_tiles[nt].e    = e;
            g_tiles[nt].row0 = off + i;
            g_tiles[nt].rows = min(TMF, c - i);
            nt++;
        }
        off += c;
    }
    g_off[NEXP] = off;
    for (int i = 0; i < T_TOKENS; i += TMF) {
        g_tiles[nt].e = NEXP; g_tiles[nt].row0 = 4096 + i; g_tiles[nt].rows = TMF;
        nt++;
    }
    g_ntiles = nt;
}

// ---------------------------------------------------------------------------
__global__ void place_kernel() {
    __shared__ int s[T_TOKENS];
    int e = blockIdx.x, t = threadIdx.x;
    int myk = -1;
    #pragma unroll
    for (int k = 0; k < TOPK; k++)
        if (g_idx[t * TOPK + k] == e) myk = k;
    s[t] = (myk >= 0) ? 1 : 0;
    __syncthreads();
    for (int off = 1; off < T_TOKENS; off <<= 1) {
        int v = (t >= off) ? s[t - off] : 0;
        __syncthreads();
        s[t] += v;
        __syncthreads();
    }
    if (myk >= 0) {
        int row = g_off[e] + s[t] - 1;
        g_row_token[row]  = t;
        g_row_weight[row] = g_w[t * TOPK + myk];
    }
}

// ---------------------------------------------------------------------------
__device__ __forceinline__ uint32_t f2tf32(float f) {
    uint32_t r;
    asm("cvt.rna.tf32.f32 %0, %1;" : "=r"(r) : "f"(f));
    return r;
}
__device__ __forceinline__ uint32_t lds_tf32(const uint32_t* p) {
    return f2tf32(__uint_as_float(*p));
}
__device__ __forceinline__ uint32_t pack_f16x2(float a, float b) {
    uint32_t r;
    asm("cvt.rn.f16x2.f32 %0, %1, %2;" : "=r"(r) : "f"(b), "f"(a));
    return r;
}

__device__ __forceinline__ void mma_tf32(float* d, const uint32_t* a, const uint32_t* b) {
    asm volatile(
        "mma.sync.aligned.m16n8k8.row.col.f32.tf32.tf32.f32 "
        "{%0,%1,%2,%3},{%4,%5,%6,%7},{%8,%9},{%0,%1,%2,%3};"
        : "+f"(d[0]), "+f"(d[1]), "+f"(d[2]), "+f"(d[3])
        : "r"(a[0]), "r"(a[1]), "r"(a[2]), "r"(a[3]), "r"(b[0]), "r"(b[1]));
}
__device__ __forceinline__ void mma_f16(float* d, const uint32_t* a, const uint32_t* b) {
    asm volatile(
        "mma.sync.aligned.m16n8k16.row.col.f32.f16.f16.f32 "
        "{%0,%1,%2,%3},{%4,%5,%6,%7},{%8,%9},{%0,%1,%2,%3};"
        : "+f"(d[0]), "+f"(d[1]), "+f"(d[2]), "+f"(d[3])
        : "r"(a[0]), "r"(a[1]), "r"(a[2]), "r"(a[3]), "r"(b[0]), "r"(b[1]));
}

__device__ __forceinline__ void cp16(uint32_t smem_dst, const void* gsrc) {
    asm volatile("cp.async.ca.shared.global [%0], [%1], 16;\n"
                 :: "r"(smem_dst), "l"(gsrc));
}
__device__ __forceinline__ void cp_commit() {
    asm volatile("cp.async.commit_group;\n");
}
__device__ __forceinline__ void cp_wait2() {
    asm volatile("cp.async.wait_group 2;\n");
}
__device__ __forceinline__ void cp_wait0() {
    asm volatile("cp.async.wait_group 0;\n");
}

// ---------------------------------------------------------------------------
// Fused expert kernel: one 64-row tile per block, 512 threads (16 warps).
__global__ __launch_bounds__(512, 1)
void fused_kernel(const float* __restrict__ x,
                  const float* __restrict__ w13,
                  const float* __restrict__ w2,
                  const float* __restrict__ w13_s,
                  const float* __restrict__ w2_s,
                  float* __restrict__ out) {
    const int tile = blockIdx.x;
    if (tile >= g_ntiles) return;
    const TileDesc td = g_tiles[tile];
    const int row0 = td.row0, rows = td.rows;
    const float* B1 = (td.e < NEXP) ? (w13 + (size_t)td.e * (2 * INTER) * DIM) : w13_s;
    const float* B2 = (td.e < NEXP) ? (w2  + (size_t)td.e * DIM * INTER)       : w2_s;

    extern __shared__ char smem[];
    uint32_t* Hs   = (uint32_t*)(smem + SM_HS);     // [64][HSTR2W] half2 words
    char*     ST   = smem + SM_ST;
    int*      rtok = (int*)(smem + SM_RTOK);
    float*    rwt  = (float*)(smem + SM_RWT);

    const int tid  = threadIdx.x;
    const int lane = tid & 31, warp = tid >> 5;
    const int wm = warp >> 3, wn = warp & 7;        // 2 (m, 32 rows) x 8 (n)
    const int g  = lane >> 2, tg = lane & 3;

    if (tid < TMF) {
        bool v = tid < rows;
        rtok[tid] = v ? g_row_token[row0 + tid] : 0;
        rwt[tid]  = v ? g_row_weight[row0 + tid] : 0.f;
    }
    __syncthreads();

    const uint32_t stBase = (uint32_t)__cvta_generic_to_shared(ST);

    // loader geometry (512 slots = 64 rows x 8 16B-chunks, 1 per thread)
    const int lr = tid >> 3, lc = (tid & 7) * 4;
    const float* aSrc  = x  + (size_t)rtok[lr] * DIM + lc;   // A (gathered)
    const float* gBase = B1 + (size_t)lr * DIM + lc;         // gate rows
    const float* uBase = gBase + (size_t)512 * DIM;          // up rows
    const uint32_t dSlot = (lr * TSTR + lc) * 4;             // byte off in stage

    // ======================= Phase 1: h = silu(x@Wg^T) * (x@Wu^T) ==========
    // Flat steps s in [0,256): nc = s>>5 (8 chunks of 64 cols), k = (s&31)*TK.
    {
        float accG[2][4], accU[2][4];
        #pragma unroll
        for (int mi = 0; mi < 2; mi++)
            #pragma unroll
            for (int q = 0; q < 4; q++) { accG[mi][q] = 0.f; accU[mi][q] = 0.f; }

        // prologue: stages for steps 0..2
        #pragma unroll
        for (int sp = 0; sp < NSTAGE - 1; sp++) {
            const int kp = sp * TK;                          // nc==0
            const uint32_t sb = stBase + sp * P1STAGE + dSlot;
            cp16(sb,             aSrc + kp);
            cp16(sb + P1ARR,     gBase + kp);
            cp16(sb + 2 * P1ARR, uBase + kp);
            cp_commit();
        }

        #pragma unroll 1
        for (int s = 0; s < 256; s++) {
            cp_wait2();
            __syncthreads();
            if (s + 3 < 256) {
                const int sp  = s + 3;
                const int ncp = sp >> 5;
                const int kp  = (sp & 31) * TK;
                const size_t boff = (size_t)ncp * 64 * DIM + kp;
                const uint32_t sb = stBase + (sp & 3) * P1STAGE + dSlot;
                cp16(sb,             aSrc + kp);
                cp16(sb + P1ARR,     gBase + boff);
                cp16(sb + 2 * P1ARR, uBase + boff);
            }
            cp_commit();
            const uint32_t* AsP = (const uint32_t*)(ST + (s & 3) * P1STAGE);
            const uint32_t* BgP = (const uint32_t*)(ST + (s & 3) * P1STAGE + P1ARR);
            const uint32_t* BuP = (const uint32_t*)(ST + (s & 3) * P1STAGE + 2 * P1ARR);
            #pragma unroll
            for (int ks = 0; ks < 4; ks++) {
                const int kk = ks * 8;
                uint32_t af[2][4], bg[2], bu[2];
                #pragma unroll
                for (int mi = 0; mi < 2; mi++) {
                    const int r = wm * 32 + mi * 16;
                    af[mi][0] = lds_tf32(&AsP[(r + g    ) * TSTR + kk + tg]);
                    af[mi][1] = lds_tf32(&AsP[(r + g + 8) * TSTR + kk + tg]);
                    af[mi][2] = lds_tf32(&AsP[(r + g    ) * TSTR + kk + tg + 4]);
                    af[mi][3] = lds_tf32(&AsP[(r + g + 8) * TSTR + kk + tg + 4]);
                }
                const int c = wn * 8 + g;
                bg[0] = lds_tf32(&BgP[c * TSTR + kk + tg]);
                bg[1] = lds_tf32(&BgP[c * TSTR + kk + tg + 4]);
                bu[0] = lds_tf32(&BuP[c * TSTR + kk + tg]);
                bu[1] = lds_tf32(&BuP[c * TSTR + kk + tg + 4]);
                #pragma unroll
                for (int mi = 0; mi < 2; mi++) {
                    mma_tf32(accG[mi], af[mi], bg);
                    mma_tf32(accU[mi], af[mi], bu);
                }
            }
            if ((s & 31) == 31) {
                // chunk epilogue: h = silu(g)*u -> Hs fp16 ; reset accs
                const int nc = s >> 5;
                #pragma unroll
                for (int mi = 0; mi < 2; mi++) {
                    const int r0 = wm * 32 + mi * 16 + g, r1 = r0 + 8;
                    const int c  = nc * 64 + wn * 8 + 2 * tg;
                    float g0 = accG[mi][0], g1 = accG[mi][1];
                    float h0 = (g0 / (1.0f + expf(-g0))) * accU[mi][0];
                    float h1 = (g1 / (1.0f + expf(-g1))) * accU[mi][1];
                    Hs[r0 * HSTR2W + (c >> 1)] = pack_f16x2(h0, h1);
                    float g2 = accG[mi][2], g3 = accG[mi][3];
                    float h2 = (g2 / (1.0f + expf(-g2))) * accU[mi][2];
                    float h3 = (g3 / (1.0f + expf(-g3))) * accU[mi][3];
                    Hs[r1 * HSTR2W + (c >> 1)] = pack_f16x2(h2, h3);
                    #pragma unroll
                    for (int q = 0; q < 4; q++) { accG[mi][q] = 0.f; accU[mi][q] = 0.f; }
                }
            }
        }
    }

    cp_wait0();
    __syncthreads();   // Hs complete, stage buffers free for phase 2

    // ======================= Phase 2: y = (h @ W2^T) * rowwt ===============
    // Flat steps s in [0,128): nb = s>>4 (8 chunks of 128 cols), k=(s&15)*TK.
    {
        // loader: 1024 slots (128 rows x 8 chunks), 2 per thread
        const int rb0 = tid >> 3, rb1 = rb0 + 64;
        const float* bBase0 = B2 + (size_t)rb0 * INTER + lc;
        const float* bBase1 = B2 + (size_t)rb1 * INTER + lc;
        const uint32_t dS0 = (rb0 * TSTR + lc) * 4;
        const uint32_t dS1 = (rb1 * TSTR + lc) * 4;

        float acc[2][2][4];
        #pragma unroll
        for (int mi = 0; mi < 2; mi++)
            #pragma unroll
            for (int ni = 0; ni < 2; ni++)
                #pragma unroll
                for (int q = 0; q < 4; q++) acc[mi][ni][q] = 0.f;

        #pragma unroll
        for (int sp = 0; sp < NSTAGE - 1; sp++) {
            const int kp = sp * TK;                          // nb==0
            const uint32_t sb = stBase + sp * P2STAGE;
            cp16(sb + dS0, bBase0 + kp);
            cp16(sb + dS1, bBase1 + kp);
            cp_commit();
        }

        #pragma unroll 1
        for (int s = 0; s < 128; s++) {
            cp_wait2();
            __syncthreads();
            if (s + 3 < 128) {
                const int sp  = s + 3;
                const int nbp = sp >> 4;
                const int kp  = (sp & 15) * TK;
                const size_t boff = (size_t)nbp * 128 * INTER + kp;
                const uint32_t sb = stBase + (sp & 3) * P2STAGE;
                cp16(sb + dS0, bBase0 + boff);
                cp16(sb + dS1, bBase1 + boff);
            }
            cp_commit();
            const float* BsP = (const float*)(ST + (s & 3) * P2STAGE);
            const int kt = (s & 15) * TK;
            #pragma unroll
            for (int ks = 0; ks < 2; ks++) {                 // two k16 sub-steps
                const int hb = (kt >> 1) + ks * 8;           // half2 word base
                uint32_t af[2][4], bf[2][2];
                #pragma unroll
                for (int mi = 0; mi < 2; mi++) {
                    const int r = wm * 32 + mi * 16;
                    af[mi][0] = Hs[(r + g    ) * HSTR2W + hb + tg];
                    af[mi][1] = Hs[(r + g + 8) * HSTR2W + hb + tg];
                    af[mi][2] = Hs[(r + g    ) * HSTR2W + hb + 4 + tg];
                    af[mi][3] = Hs[(r + g + 8) * HSTR2W + hb + 4 + tg];
                }
                #pragma unroll
                for (int ni = 0; ni < 2; ni++) {
                    const int rloc = wn * 16 + ni * 8 + g;   // 0..127
                    const float* row = BsP + rloc * TSTR + ks * 16;
                    float2 p0 = *(const float2*)(row + 2 * tg);
                    float2 p1 = *(const float2*)(row + 8 + 2 * tg);
                    bf[ni][0] = pack_f16x2(p0.x, p0.y);
                    bf[ni][1] = pack_f16x2(p1.x, p1.y);
                }
                #pragma unroll
                for (int mi = 0; mi < 2; mi++)
                    #pragma unroll
                    for (int ni = 0; ni < 2; ni++)
                        mma_f16(acc[mi][ni], af[mi], bf[ni]);
            }
            if ((s & 15) == 15) {
                // chunk epilogue: weighted atomic accumulate; reset accs
                const int nb = s >> 4;
                #pragma unroll
                for (int mi = 0; mi < 2; mi++) {
                    const int r0 = wm * 32 + mi * 16 + g, r1 = r0 + 8;
                    const float w0 = rwt[r0], w1 = rwt[r1];
                    const int   t0 = rtok[r0], t1 = rtok[r1];
                    #pragma unroll
                    for (int ni = 0; ni < 2; ni++) {
                        const int col = nb * 128 + wn * 16 + ni * 8 + 2 * tg;
                        float* q0 = out + (size_t)t0 * DIM + col;
                        float* q1 = out + (size_t)t1 * DIM + col;
                        atomicAdd(q0 + 0, acc[mi][ni][0] * w0);
                        atomicAdd(q0 + 1, acc[mi][ni][1] * w0);
                        atomicAdd(q1 + 0, acc[mi][ni][2] * w1);
                        atomicAdd(q1 + 1, acc[mi][ni][3] * w1);
                        #pragma unroll
                        for (int q = 0; q < 4; q++) acc[mi][ni][q] = 0.f;
                    }
                }
            }
        }
    }
}

// ---------------------------------------------------------------------------
namespace {
struct EagerInit {
    EagerInit() {
        cudaFuncAttributes a;
        (void)cudaFuncGetAttributes(&a, (const void*)init_kernel);
        (void)cudaFuncGetAttributes(&a, (const void*)gate_kernel);
        (void)cudaFuncGetAttributes(&a, (const void*)sched_kernel);
        (void)cudaFuncGetAttributes(&a, (const void*)place_kernel);
        (void)cudaFuncGetAttributes(&a, (const void*)fused_kernel);
        (void)cudaFuncSetAttribute((const void*)fused_kernel,
                                   cudaFuncAttributeMaxDynamicSharedMemorySize, SM_TOTAL);
        int zeros[NEXP];
        memset(zeros, 0, sizeof(zeros));
        (void)cudaMemcpyToSymbol(g_counts, zeros, sizeof(zeros));
        init_kernel<<<1, 32>>>();
        (void)cudaDeviceSynchronize();
        (void)cudaGetLastError();
    }
};
static EagerInit eager_init_instance;
}  // namespace

// ---------------------------------------------------------------------------
extern "C" void kernel_launch(void* const* d_in, const int* in_sizes, int n_in,
                              void* d_out, int out_size) {
    const float* x     = (const float*)d_in[0];
    const float* gw    = (const float*)d_in[2];
    const float* gb    = (const float*)d_in[3];
    const float* w13   = (const float*)d_in[4];
    const float* w2    = (const float*)d_in[5];
    const float* w13_s = (const float*)d_in[6];
    const float* w2_s  = (const float*)d_in[7];
    float* out = (float*)d_out;

    (void)cudaFuncSetAttribute((const void*)fused_kernel,
                               cudaFuncAttributeMaxDynamicSharedMemorySize, SM_TOTAL);

    cudaMemsetAsync(out, 0, (size_t)out_size * sizeof(float), 0);
    init_kernel<<<1, 32>>>();
    gate_kernel<<<T_TOKENS / 8, 256>>>(x, gw, gb);
    sched_kernel<<<1, 1>>>();
    place_kernel<<<NEXP, T_TOKENS>>>();
    fused_kernel<<<MAXT, 512, SM_TOTAL>>>(x, w13, w2, w13_s, w2_s, out);
}